// round 13
// baseline (speedup 1.0000x reference)
#include <cuda_runtime.h>
#include <cuda_fp16.h>
#include <math.h>
#include <stdint.h>

#define NN 100000
#define NE 3200000
#define F_IN 512
#define F_HID 256
#define F_OUT 16
#define KSTEPS 10
#define ALPHA 0.1f

#define NB_SCAN 98              // ceil(100000/1024)
#define MLP_GY 782              // ceil(100000/128)

// ---- static scratch ----
__device__ uint2 g_hy16 [NN * 4];           // dinv * h  (alpha term, fp16 x16)
__device__ float g_hpart[NN * F_OUT];       // complete h (pre-bias-dinv) from MLP
__device__ uint2 g_yA[NN * 4];              // y in fp16: 16 halfs = 4x uint2 per node
__device__ uint2 g_yB[NN * 4];
__device__ float g_dinv[NN];
__device__ int   g_counts[NN];
__device__ int   g_ptr[NN + 1];
__device__ int   g_cursor[NN];
__device__ int   g_bsums[NB_SCAN];
__device__ int   g_boff [NB_SCAN];
__device__ int   g_esrc[NE];                // src only (y-space: no weights)

// ------------------------------------------------------------------
// CSR construction (edge_index is int32)
// ------------------------------------------------------------------
__global__ void __launch_bounds__(256) k_zero_counts() {
    int i = blockIdx.x * blockDim.x + threadIdx.x;
    if (i < NN) g_counts[i] = 0;
}

__global__ void __launch_bounds__(256) k_count(const int* __restrict__ dst) {
    int e = blockIdx.x * blockDim.x + threadIdx.x;
    if (e < NE) atomicAdd(&g_counts[dst[e]], 1);
}

__global__ void __launch_bounds__(256) k_dinv() {
    int i = blockIdx.x * blockDim.x + threadIdx.x;
    if (i < NN) g_dinv[i] = rsqrtf((float)(g_counts[i] + 1));
}

__global__ void __launch_bounds__(1024) k_scan1() {
    __shared__ int s[1024];
    int b = blockIdx.x, t = threadIdx.x;
    int idx = b * 1024 + t;
    int v = (idx < NN) ? g_counts[idx] : 0;
    s[t] = v;
    __syncthreads();
    for (int off = 1; off < 1024; off <<= 1) {
        int u = (t >= off) ? s[t - off] : 0;
        __syncthreads();
        s[t] += u;
        __syncthreads();
    }
    if (idx < NN) g_ptr[idx] = s[t] - v;
    if (t == 1023) g_bsums[b] = s[1023];
}

__global__ void __launch_bounds__(128) k_scan2() {
    __shared__ int s[128];
    int t = threadIdx.x;
    int v = (t < NB_SCAN) ? g_bsums[t] : 0;
    s[t] = v;
    __syncthreads();
    for (int off = 1; off < 128; off <<= 1) {
        int u = (t >= off) ? s[t - off] : 0;
        __syncthreads();
        s[t] += u;
        __syncthreads();
    }
    if (t < NB_SCAN) g_boff[t] = s[t] - v;
    if (t == 127) g_ptr[NN] = s[127];
}

__global__ void __launch_bounds__(1024) k_scan3() {
    int idx = blockIdx.x * 1024 + threadIdx.x;
    if (idx < NN) {
        int p = g_ptr[idx] + g_boff[blockIdx.x];
        g_ptr[idx] = p;
        g_cursor[idx] = p;
    }
}

__global__ void __launch_bounds__(256) k_fill(const int* __restrict__ src,
                                              const int* __restrict__ dst) {
    int e = blockIdx.x * blockDim.x + threadIdx.x;
    if (e < NE) {
        int s = src[e];
        int d = dst[e];
        int pos = atomicAdd(&g_cursor[d], 1);
        g_esrc[pos] = s;
    }
}

// ------------------------------------------------------------------
// Fused MLP: bf16 m16n8k16 mma, full 256-column tile (X read ONCE).
// grid = (1, 782), block = 512 (16 warps: 4M x 4N, warp tile 32x64)
// ------------------------------------------------------------------
#define XS_STRIDE 36
#define XSTG (128 * XS_STRIDE)              // X stage floats
#define WSTG (256 * XS_STRIDE)              // W stage floats
#define HS2 130                             // uint stride for bf16 h1 tile (128+2)
#define SMEM_FLOATS (2 * XSTG + 2 * WSTG + 16 * HS2)
#define SMEM_BYTES  (SMEM_FLOATS * 4)

__device__ __forceinline__ uint32_t f2bf2(float lo, float hi) {
    uint32_t r;
    asm("cvt.rn.bf16x2.f32 %0, %1, %2;" : "=r"(r) : "f"(hi), "f"(lo));
    return r;
}

__device__ __forceinline__ void cp_async16(float* smem_dst, const float* gsrc, int src_bytes) {
    uint32_t s = (uint32_t)__cvta_generic_to_shared(smem_dst);
    asm volatile("cp.async.cg.shared.global [%0], [%1], 16, %2;\n"
                 :: "r"(s), "l"(gsrc), "r"(src_bytes));
}
__device__ __forceinline__ void cp_commit() { asm volatile("cp.async.commit_group;\n"); }
__device__ __forceinline__ void cp_wait1() { asm volatile("cp.async.wait_group 1;\n"); }
__device__ __forceinline__ void cp_wait0() { asm volatile("cp.async.wait_group 0;\n"); }

__device__ __forceinline__ void mma_bf16(float* d, const uint32_t* a, const uint32_t* b) {
    asm volatile(
        "mma.sync.aligned.m16n8k16.row.col.f32.bf16.bf16.f32 "
        "{%0,%1,%2,%3}, {%4,%5,%6,%7}, {%8,%9}, {%0,%1,%2,%3};"
        : "+f"(d[0]), "+f"(d[1]), "+f"(d[2]), "+f"(d[3])
        : "r"(a[0]), "r"(a[1]), "r"(a[2]), "r"(a[3]), "r"(b[0]), "r"(b[1]));
}

__global__ void __launch_bounds__(512)
k_mlp(const float* __restrict__ X, const float* __restrict__ W1,
      const float* __restrict__ b1, const float* __restrict__ W2) {
    extern __shared__ float smem[];
    float* Xst = smem;                        // [2][128][36] raw fp32 stages
    float* Wst = smem + 2 * XSTG;             // [2][256][36]
    uint32_t* Hu  = (uint32_t*)smem;          // bf16 h1 tile [128][130] (unions stages)
    uint32_t* W2u = (uint32_t*)(smem + 2 * XSTG + 2 * WSTG);  // bf16 W2 [16][130]

    const int tid  = threadIdx.x;
    const int lane = tid & 31;
    const int warp = tid >> 5;
    const int row0 = blockIdx.y * 128;
    const int wm = (warp & 3) * 32;           // 4 M-warps
    const int wn = (warp >> 2) * 64;          // 4 N-warps over 256 cols
    const int grp  = lane >> 2;
    const int thr4 = lane & 3;

    // preload full W2 as bf16 pairs: W2u[n][kq] = bf16x2(W2[n][2kq], W2[n][2kq+1])
    for (int i = tid; i < 16 * 128; i += 512) {
        int n = i >> 7, kq = i & 127;
        float2 w = *(const float2*)(W2 + n * F_HID + kq * 2);
        W2u[n * HS2 + kq] = f2bf2(w.x, w.y);
    }

    float acc[2][8][4];
#pragma unroll
    for (int mt = 0; mt < 2; mt++)
#pragma unroll
        for (int nt = 0; nt < 8; nt++)
#pragma unroll
            for (int q = 0; q < 4; q++) acc[mt][nt][q] = 0.f;

    auto stage = [&](int s, int st) {
        // X: 128 rows x 32 k = 1024 16B-chunks; 512 threads x 2
#pragma unroll
        for (int it = 0; it < 2; it++) {
            int idx = tid + 512 * it;
            int m  = idx >> 3;
            int kq = (idx & 7) * 4;
            int gr = row0 + m;
            int valid = (gr < NN) ? 16 : 0;
            const float* xs = X + (size_t)((gr < NN) ? gr : 0) * F_IN + s * 32 + kq;
            cp_async16(Xst + st * XSTG + m * XS_STRIDE + kq, xs, valid);
        }
        // W1: 256 rows x 32 k = 2048 chunks; 512 threads x 4
#pragma unroll
        for (int it = 0; it < 4; it++) {
            int idx = tid + 512 * it;
            int m  = idx >> 3;
            int kq = (idx & 7) * 4;
            const float* ws = W1 + (size_t)m * F_IN + s * 32 + kq;
            cp_async16(Wst + st * WSTG + m * XS_STRIDE + kq, ws, 16);
        }
    };

    stage(0, 0);
    cp_commit();

    for (int s = 0; s < 16; s++) {
        int cur = s & 1;
        if (s < 15) {
            stage(s + 1, cur ^ 1);
            cp_commit();
            cp_wait1();
        } else {
            cp_wait0();
        }
        __syncthreads();

        const float* Xs = Xst + cur * XSTG;
        const float* Ws = Wst + cur * WSTG;
#pragma unroll
        for (int kk = 0; kk < 32; kk += 16) {
            uint32_t af[2][4], bf[8][2];
#pragma unroll
            for (int mt = 0; mt < 2; mt++) {
                int r = wm + mt * 16 + grp;
                float2 p0 = *(const float2*)(Xs + r * XS_STRIDE + kk + thr4 * 2);
                float2 p1 = *(const float2*)(Xs + (r + 8) * XS_STRIDE + kk + thr4 * 2);
                float2 p2 = *(const float2*)(Xs + r * XS_STRIDE + kk + 8 + thr4 * 2);
                float2 p3 = *(const float2*)(Xs + (r + 8) * XS_STRIDE + kk + 8 + thr4 * 2);
                af[mt][0] = f2bf2(p0.x, p0.y);
                af[mt][1] = f2bf2(p1.x, p1.y);
                af[mt][2] = f2bf2(p2.x, p2.y);
                af[mt][3] = f2bf2(p3.x, p3.y);
            }
#pragma unroll
            for (int nt = 0; nt < 8; nt++) {
                int n = wn + nt * 8 + grp;
                float2 q0 = *(const float2*)(Ws + n * XS_STRIDE + kk + thr4 * 2);
                float2 q1 = *(const float2*)(Ws + n * XS_STRIDE + kk + 8 + thr4 * 2);
                bf[nt][0] = f2bf2(q0.x, q0.y);
                bf[nt][1] = f2bf2(q1.x, q1.y);
            }
#pragma unroll
            for (int mt = 0; mt < 2; mt++)
#pragma unroll
                for (int nt = 0; nt < 8; nt++)
                    mma_bf16(acc[mt][nt], af[mt], bf[nt]);
        }
        __syncthreads();
    }
    __syncthreads();   // stages dead; Hu reuses them

    // epilogue: relu(acc + b1) -> Hu (bf16 pairs), cols 0..255
#pragma unroll
    for (int mt = 0; mt < 2; mt++) {
        int r = wm + mt * 16 + grp;
#pragma unroll
        for (int nt = 0; nt < 8; nt++) {
            int c = wn + nt * 8 + thr4 * 2;
            float b1a = __ldg(b1 + c);
            float b1b = __ldg(b1 + c + 1);
            float v0 = fmaxf(acc[mt][nt][0] + b1a, 0.f);
            float v1 = fmaxf(acc[mt][nt][1] + b1b, 0.f);
            float v2 = fmaxf(acc[mt][nt][2] + b1a, 0.f);
            float v3 = fmaxf(acc[mt][nt][3] + b1b, 0.f);
            int cq = (c >> 1);
            Hu[r * HS2 + cq]       = f2bf2(v0, v1);
            Hu[(r + 8) * HS2 + cq] = f2bf2(v2, v3);
        }
    }
    __syncthreads();

    // GEMM2 via bf16 mma: D[128x16] = H[128x256] @ W2^T[256x16]; warps 0..7
    if (warp < 8) {
        float a2[2][4];
#pragma unroll
        for (int nt2 = 0; nt2 < 2; nt2++)
#pragma unroll
            for (int q = 0; q < 4; q++) a2[nt2][q] = 0.f;

        int rA = warp * 16 + grp;
#pragma unroll
        for (int kt = 0; kt < 16; kt++) {
            uint32_t a[4];
            a[0] = Hu[rA * HS2 + kt * 8 + thr4];
            a[1] = Hu[(rA + 8) * HS2 + kt * 8 + thr4];
            a[2] = Hu[rA * HS2 + kt * 8 + thr4 + 4];
            a[3] = Hu[(rA + 8) * HS2 + kt * 8 + thr4 + 4];
#pragma unroll
            for (int nt2 = 0; nt2 < 2; nt2++) {
                int n = nt2 * 8 + grp;
                uint32_t bb[2] = { W2u[n * HS2 + kt * 8 + thr4],
                                   W2u[n * HS2 + kt * 8 + thr4 + 4] };
                mma_bf16(a2[nt2], a, bb);
            }
        }

#pragma unroll
        for (int nt2 = 0; nt2 < 2; nt2++) {
            int c = nt2 * 8 + thr4 * 2;
            int gr0 = row0 + rA;
            int gr1 = gr0 + 8;
            if (gr0 < NN)
                *(float2*)&g_hpart[gr0 * F_OUT + c] = make_float2(a2[nt2][0], a2[nt2][1]);
            if (gr1 < NN)
                *(float2*)&g_hpart[gr1 * F_OUT + c] = make_float2(a2[nt2][2], a2[nt2][3]);
        }
    }
}

// h + b2 -> hy = dinv*h; store hy (fp16) and y0 = hy (fp16)
__global__ void __launch_bounds__(256) k_hcombine(const float* __restrict__ b2) {
    int i = blockIdx.x * blockDim.x + threadIdx.x;   // over NN*4 quads
    if (i < NN * 4) {
        int node = i >> 2;
        const float4* p0 = (const float4*)g_hpart;
        const float4* b4 = (const float4*)b2;
        float4 a = p0[i], c = __ldg(&b4[i & 3]);
        float di = g_dinv[node];
        float hx = (a.x + c.x) * di;
        float hyv = (a.y + c.y) * di;
        float hz = (a.z + c.z) * di;
        float hw = (a.w + c.w) * di;
        __half2 ha = __floats2half2_rn(hx, hyv);
        __half2 hb = __floats2half2_rn(hz, hw);
        uint2 w;
        w.x = *(uint32_t*)&ha;
        w.y = *(uint32_t*)&hb;
        g_hy16[i] = w;
        g_yA[i] = w;
    }
}

// ------------------------------------------------------------------
// Propagation in y-space (fp16 storage, fp32 accumulation)
// ------------------------------------------------------------------
__device__ __forceinline__ float4 y16_to_f4(uint2 r) {
    __half2 p0 = *(__half2*)&r.x;
    __half2 p1 = *(__half2*)&r.y;
    float2 f0 = __half22float2(p0);
    float2 f1 = __half22float2(p1);
    return make_float4(f0.x, f0.y, f1.x, f1.y);
}

__device__ __forceinline__ float4 prop_node_y(const uint2* __restrict__ yin,
                                              int node, int tc) {
    int s = g_ptr[node], e = g_ptr[node + 1];
    float4 acc = make_float4(0.f, 0.f, 0.f, 0.f);
    int j = s;
    for (; j + 1 < e; j += 2) {
        int s0 = __ldg(&g_esrc[j]);
        int s1 = __ldg(&g_esrc[j + 1]);
        float4 v0 = y16_to_f4(__ldg(&yin[s0 * 4 + tc]));
        float4 v1 = y16_to_f4(__ldg(&yin[s1 * 4 + tc]));
        acc.x += v0.x + v1.x;
        acc.y += v0.y + v1.y;
        acc.z += v0.z + v1.z;
        acc.w += v0.w + v1.w;
    }
    if (j < e) {
        int s0 = __ldg(&g_esrc[j]);
        float4 v0 = y16_to_f4(__ldg(&yin[s0 * 4 + tc]));
        acc.x += v0.x;
        acc.y += v0.y;
        acc.z += v0.z;
        acc.w += v0.w;
    }
    float4 vs = y16_to_f4(__ldg(&yin[node * 4 + tc]));
    float di = g_dinv[node];
    float c1 = (1.f - ALPHA) * di * di;
    float4 hy = y16_to_f4(__ldg(&g_hy16[node * 4 + tc]));
    float4 o;
    o.x = c1 * (acc.x + vs.x) + ALPHA * hy.x;
    o.y = c1 * (acc.y + vs.y) + ALPHA * hy.y;
    o.z = c1 * (acc.z + vs.z) + ALPHA * hy.z;
    o.w = c1 * (acc.w + vs.w) + ALPHA * hy.w;
    return o;
}

__global__ void __launch_bounds__(256) k_prop(int a_to_b) {
    const uint2* yin = a_to_b ? g_yA : g_yB;
    uint2* yout = a_to_b ? g_yB : g_yA;
    int node = blockIdx.x * 64 + (threadIdx.x >> 2);
    int tc = threadIdx.x & 3;
    if (node >= NN) return;
    float4 o = prop_node_y(yin, node, tc);
    __half2 ha = __floats2half2_rn(o.x, o.y);
    __half2 hb = __floats2half2_rn(o.z, o.w);
    uint2 w;
    w.x = *(uint32_t*)&ha;
    w.y = *(uint32_t*)&hb;
    yout[node * 4 + tc] = w;
}

// final step: y (fp32 regs) -> z = y/dinv -> log_softmax -> out. reads g_yB.
__global__ void __launch_bounds__(256) k_prop_lsm(float* __restrict__ out) {
    int node = blockIdx.x * 64 + (threadIdx.x >> 2);
    int tc = threadIdx.x & 3;
    if (node >= NN) return;
    float4 y = prop_node_y(g_yB, node, tc);
    float inv_di = 1.f / g_dinv[node];          // sqrt(deg)
    float4 v;
    v.x = y.x * inv_di; v.y = y.y * inv_di; v.z = y.z * inv_di; v.w = y.w * inv_di;
    float m = fmaxf(fmaxf(v.x, v.y), fmaxf(v.z, v.w));
    m = fmaxf(m, __shfl_xor_sync(0xffffffffu, m, 1, 4));
    m = fmaxf(m, __shfl_xor_sync(0xffffffffu, m, 2, 4));
    float s = expf(v.x - m) + expf(v.y - m) + expf(v.z - m) + expf(v.w - m);
    s += __shfl_xor_sync(0xffffffffu, s, 1, 4);
    s += __shfl_xor_sync(0xffffffffu, s, 2, 4);
    float ls = m + logf(s);
    float4 r;
    r.x = v.x - ls; r.y = v.y - ls; r.z = v.z - ls; r.w = v.w - ls;
    ((float4*)out)[node * 4 + tc] = r;
}

// ------------------------------------------------------------------
extern "C" void kernel_launch(void* const* d_in, const int* in_sizes, int n_in,
                              void* d_out, int out_size) {
    const float* x  = (const float*)d_in[0];
    const float* W1 = (const float*)d_in[1];
    const float* b1 = (const float*)d_in[2];
    const float* W2 = (const float*)d_in[3];
    const float* b2 = (const float*)d_in[4];
    const int* ei = (const int*)d_in[5];
    const int* src = ei;
    const int* dst = ei + NE;
    float* out = (float*)d_out;

    static cudaStream_t s_csr = nullptr;
    static cudaEvent_t ev_fork = nullptr, ev_dinv = nullptr, ev_join = nullptr;
    static bool init_done = false;
    if (!init_done) {
        cudaStreamCreateWithFlags(&s_csr, cudaStreamNonBlocking);
        cudaEventCreateWithFlags(&ev_fork, cudaEventDisableTiming);
        cudaEventCreateWithFlags(&ev_dinv, cudaEventDisableTiming);
        cudaEventCreateWithFlags(&ev_join, cudaEventDisableTiming);
        cudaFuncSetAttribute(k_mlp, cudaFuncAttributeMaxDynamicSharedMemorySize, SMEM_BYTES);
        init_done = true;
    }

    // fork
    cudaEventRecord(ev_fork, 0);
    cudaStreamWaitEvent(s_csr, ev_fork, 0);

    // --- CSR branch ---
    k_zero_counts<<<(NN + 255) / 256, 256, 0, s_csr>>>();
    k_count<<<(NE + 255) / 256, 256, 0, s_csr>>>(dst);
    k_dinv<<<(NN + 255) / 256, 256, 0, s_csr>>>();
    cudaEventRecord(ev_dinv, s_csr);        // dinv ready early for hcombine
    k_scan1<<<NB_SCAN, 1024, 0, s_csr>>>();
    k_scan2<<<1, 128, 0, s_csr>>>();
    k_scan3<<<NB_SCAN, 1024, 0, s_csr>>>();
    k_fill<<<(NE + 255) / 256, 256, 0, s_csr>>>(src, dst);
    cudaEventRecord(ev_join, s_csr);

    // --- MLP branch (default stream) ---
    dim3 gm(1, MLP_GY);
    k_mlp<<<gm, 512, SMEM_BYTES>>>(x, W1, b1, W2);
    cudaStreamWaitEvent(0, ev_dinv, 0);     // hcombine needs dinv
    k_hcombine<<<(NN * 4 + 255) / 256, 256>>>(b2);

    // join (prop needs CSR)
    cudaStreamWaitEvent(0, ev_join, 0);

    // 9 intermediate y-steps (A->B->A...), step 8 ends in B; final fused step reads B
    for (int s = 0; s < KSTEPS - 1; s++)
        k_prop<<<(NN + 63) / 64, 256>>>((s & 1) ? 0 : 1);
    k_prop_lsm<<<(NN + 63) / 64, 256>>>(out);
}

// round 14
// speedup vs baseline: 1.0485x; 1.0485x over previous
#include <cuda_runtime.h>
#include <cuda_fp16.h>
#include <math.h>
#include <stdint.h>

#define NN 100000
#define NE 3200000
#define F_IN 512
#define F_HID 256
#define F_OUT 16
#define KSTEPS 10
#define ALPHA 0.1f

#define NB_SCAN 98              // ceil(100000/1024)
#define MLP_GY 782              // ceil(100000/128)

// ---- static scratch ----
__device__ uint2 g_hy16 [NN * 4];           // dinv * h  (alpha term, fp16 x16)
__device__ float g_hpart[2][NN * F_OUT];    // per-column-half GEMM2 partials
__device__ uint2 g_yA[NN * 4];              // y in fp16: 16 halfs = 4x uint2 per node
__device__ uint2 g_yB[NN * 4];
__device__ float g_dinv[NN];
__device__ int   g_counts[NN];
__device__ int   g_ptr[NN + 1];
__device__ int   g_cursor[NN];
__device__ int   g_bsums[NB_SCAN];
__device__ int   g_boff [NB_SCAN];
__device__ int   g_esrc[NE];                // src only (y-space: no weights)

// ------------------------------------------------------------------
// CSR construction (edge_index is int32)
// ------------------------------------------------------------------
__global__ void __launch_bounds__(256) k_zero_counts() {
    int i = blockIdx.x * blockDim.x + threadIdx.x;
    if (i < NN) g_counts[i] = 0;
}

// two edges per thread via int2 load (NE is even)
__global__ void __launch_bounds__(256) k_count(const int2* __restrict__ dst2) {
    int e = blockIdx.x * blockDim.x + threadIdx.x;
    if (e < NE / 2) {
        int2 d = __ldg(&dst2[e]);
        atomicAdd(&g_counts[d.x], 1);
        atomicAdd(&g_counts[d.y], 1);
    }
}

__global__ void __launch_bounds__(256) k_dinv() {
    int i = blockIdx.x * blockDim.x + threadIdx.x;
    if (i < NN) g_dinv[i] = rsqrtf((float)(g_counts[i] + 1));
}

__global__ void __launch_bounds__(1024) k_scan1() {
    __shared__ int s[1024];
    int b = blockIdx.x, t = threadIdx.x;
    int idx = b * 1024 + t;
    int v = (idx < NN) ? g_counts[idx] : 0;
    s[t] = v;
    __syncthreads();
    for (int off = 1; off < 1024; off <<= 1) {
        int u = (t >= off) ? s[t - off] : 0;
        __syncthreads();
        s[t] += u;
        __syncthreads();
    }
    if (idx < NN) g_ptr[idx] = s[t] - v;
    if (t == 1023) g_bsums[b] = s[1023];
}

__global__ void __launch_bounds__(128) k_scan2() {
    __shared__ int s[128];
    int t = threadIdx.x;
    int v = (t < NB_SCAN) ? g_bsums[t] : 0;
    s[t] = v;
    __syncthreads();
    for (int off = 1; off < 128; off <<= 1) {
        int u = (t >= off) ? s[t - off] : 0;
        __syncthreads();
        s[t] += u;
        __syncthreads();
    }
    if (t < NB_SCAN) g_boff[t] = s[t] - v;
    if (t == 127) g_ptr[NN] = s[127];
}

__global__ void __launch_bounds__(1024) k_scan3() {
    int idx = blockIdx.x * 1024 + threadIdx.x;
    if (idx < NN) {
        int p = g_ptr[idx] + g_boff[blockIdx.x];
        g_ptr[idx] = p;
        g_cursor[idx] = p;
    }
}

__global__ void __launch_bounds__(256) k_fill(const int* __restrict__ src,
                                              const int* __restrict__ dst) {
    int e = blockIdx.x * blockDim.x + threadIdx.x;
    if (e < NE) {
        int s = src[e];
        int d = dst[e];
        int pos = atomicAdd(&g_cursor[d], 1);
        g_esrc[pos] = s;
    }
}

// ------------------------------------------------------------------
// Fused MLP: bf16 m16n8k16 mma for GEMM1 and GEMM2. (round-12 version)
// grid = (2, 782), block = 256 (8 warps, warp grid 4M x 2N, warp tile 32x64)
// ------------------------------------------------------------------
#define XS_STRIDE 36
#define STAGE_FLOATS (128 * XS_STRIDE)
#define HS2 66                              // uint stride for bf16 h1 tile (64+2 pad)
#define W2U_FLOATS (16 * HS2)
#define SMEM_FLOATS (4 * STAGE_FLOATS + W2U_FLOATS)
#define SMEM_BYTES  (SMEM_FLOATS * 4)

__device__ __forceinline__ uint32_t f2bf2(float lo, float hi) {
    uint32_t r;
    asm("cvt.rn.bf16x2.f32 %0, %1, %2;" : "=r"(r) : "f"(hi), "f"(lo));
    return r;
}

__device__ __forceinline__ void cp_async16(float* smem_dst, const float* gsrc, int src_bytes) {
    uint32_t s = (uint32_t)__cvta_generic_to_shared(smem_dst);
    asm volatile("cp.async.cg.shared.global [%0], [%1], 16, %2;\n"
                 :: "r"(s), "l"(gsrc), "r"(src_bytes));
}
__device__ __forceinline__ void cp_commit() { asm volatile("cp.async.commit_group;\n"); }
__device__ __forceinline__ void cp_wait1() { asm volatile("cp.async.wait_group 1;\n"); }
__device__ __forceinline__ void cp_wait0() { asm volatile("cp.async.wait_group 0;\n"); }

__device__ __forceinline__ void mma_bf16(float* d, const uint32_t* a, const uint32_t* b) {
    asm volatile(
        "mma.sync.aligned.m16n8k16.row.col.f32.bf16.bf16.f32 "
        "{%0,%1,%2,%3}, {%4,%5,%6,%7}, {%8,%9}, {%0,%1,%2,%3};"
        : "+f"(d[0]), "+f"(d[1]), "+f"(d[2]), "+f"(d[3])
        : "r"(a[0]), "r"(a[1]), "r"(a[2]), "r"(a[3]), "r"(b[0]), "r"(b[1]));
}

__global__ void __launch_bounds__(256)
k_mlp(const float* __restrict__ X, const float* __restrict__ W1,
      const float* __restrict__ b1, const float* __restrict__ W2) {
    extern __shared__ float smem[];
    float* Xst = smem;                        // [2][128][36] raw fp32 stages
    float* Wst = smem + 2 * STAGE_FLOATS;     // [2][128][36]
    uint32_t* Hu  = (uint32_t*)smem;          // bf16 h1 tile [128][66] (unions stages)
    uint32_t* W2u = (uint32_t*)(smem + 4 * STAGE_FLOATS);  // bf16 W2 [16][66]

    const int tid  = threadIdx.x;
    const int lane = tid & 31;
    const int warp = tid >> 5;
    const int row0 = blockIdx.y * 128;
    const int col0 = blockIdx.x * 128;
    const int wm = (warp & 3) * 32;
    const int wn = (warp >> 2) * 64;
    const int grp  = lane >> 2;
    const int thr4 = lane & 3;

    // preload W2 slice as bf16 pairs
    for (int i = tid; i < 16 * 64; i += 256) {
        int n = i >> 6, kq = i & 63;
        float2 w = *(const float2*)(W2 + n * F_HID + col0 + kq * 2);
        W2u[n * HS2 + kq] = f2bf2(w.x, w.y);
    }

    float acc[2][8][4];
#pragma unroll
    for (int mt = 0; mt < 2; mt++)
#pragma unroll
        for (int nt = 0; nt < 8; nt++)
#pragma unroll
            for (int q = 0; q < 4; q++) acc[mt][nt][q] = 0.f;

    auto stage = [&](int s, int st) {
#pragma unroll
        for (int it = 0; it < 4; it++) {
            int idx = tid + 256 * it;
            int m  = idx >> 3;
            int kq = (idx & 7) * 4;
            int gr = row0 + m;
            int valid = (gr < NN) ? 16 : 0;
            const float* xs = X + (size_t)((gr < NN) ? gr : 0) * F_IN + s * 32 + kq;
            cp_async16(Xst + st * STAGE_FLOATS + m * XS_STRIDE + kq, xs, valid);
            const float* ws = W1 + (size_t)(col0 + m) * F_IN + s * 32 + kq;
            cp_async16(Wst + st * STAGE_FLOATS + m * XS_STRIDE + kq, ws, 16);
        }
    };

    stage(0, 0);
    cp_commit();

    for (int s = 0; s < 16; s++) {
        int cur = s & 1;
        if (s < 15) {
            stage(s + 1, cur ^ 1);
            cp_commit();
            cp_wait1();
        } else {
            cp_wait0();
        }
        __syncthreads();

        const float* Xs = Xst + cur * STAGE_FLOATS;
        const float* Ws = Wst + cur * STAGE_FLOATS;
#pragma unroll
        for (int kk = 0; kk < 32; kk += 16) {
            uint32_t af[2][4], bf[8][2];
#pragma unroll
            for (int mt = 0; mt < 2; mt++) {
                int r = wm + mt * 16 + grp;
                float2 p0 = *(const float2*)(Xs + r * XS_STRIDE + kk + thr4 * 2);
                float2 p1 = *(const float2*)(Xs + (r + 8) * XS_STRIDE + kk + thr4 * 2);
                float2 p2 = *(const float2*)(Xs + r * XS_STRIDE + kk + 8 + thr4 * 2);
                float2 p3 = *(const float2*)(Xs + (r + 8) * XS_STRIDE + kk + 8 + thr4 * 2);
                af[mt][0] = f2bf2(p0.x, p0.y);
                af[mt][1] = f2bf2(p1.x, p1.y);
                af[mt][2] = f2bf2(p2.x, p2.y);
                af[mt][3] = f2bf2(p3.x, p3.y);
            }
#pragma unroll
            for (int nt = 0; nt < 8; nt++) {
                int n = wn + nt * 8 + grp;
                float2 q0 = *(const float2*)(Ws + n * XS_STRIDE + kk + thr4 * 2);
                float2 q1 = *(const float2*)(Ws + n * XS_STRIDE + kk + 8 + thr4 * 2);
                bf[nt][0] = f2bf2(q0.x, q0.y);
                bf[nt][1] = f2bf2(q1.x, q1.y);
            }
#pragma unroll
            for (int mt = 0; mt < 2; mt++)
#pragma unroll
                for (int nt = 0; nt < 8; nt++)
                    mma_bf16(acc[mt][nt], af[mt], bf[nt]);
        }
        __syncthreads();
    }
    // stage buffers now dead; Hu reuses them
    __syncthreads();

    // epilogue: relu(acc + b1) -> Hu (bf16 pairs)
#pragma unroll
    for (int mt = 0; mt < 2; mt++) {
        int r = wm + mt * 16 + grp;
#pragma unroll
        for (int nt = 0; nt < 8; nt++) {
            int c = wn + nt * 8 + thr4 * 2;
            float b1a = __ldg(b1 + col0 + c);
            float b1b = __ldg(b1 + col0 + c + 1);
            float v0 = fmaxf(acc[mt][nt][0] + b1a, 0.f);
            float v1 = fmaxf(acc[mt][nt][1] + b1b, 0.f);
            float v2 = fmaxf(acc[mt][nt][2] + b1a, 0.f);
            float v3 = fmaxf(acc[mt][nt][3] + b1b, 0.f);
            int cq = (c >> 1);
            Hu[r * HS2 + cq]       = f2bf2(v0, v1);
            Hu[(r + 8) * HS2 + cq] = f2bf2(v2, v3);
        }
    }
    __syncthreads();

    // GEMM2 via bf16 mma: D[128x16] = H[128x128] @ W2slice^T[128x16]
    {
        float a2[2][4];
#pragma unroll
        for (int nt2 = 0; nt2 < 2; nt2++)
#pragma unroll
            for (int q = 0; q < 4; q++) a2[nt2][q] = 0.f;

        int rA = warp * 16 + grp;
#pragma unroll
        for (int kt = 0; kt < 8; kt++) {
            uint32_t a[4], b0[2], b1v[2];
            a[0] = Hu[rA * HS2 + kt * 8 + thr4];
            a[1] = Hu[(rA + 8) * HS2 + kt * 8 + thr4];
            a[2] = Hu[rA * HS2 + kt * 8 + thr4 + 4];
            a[3] = Hu[(rA + 8) * HS2 + kt * 8 + thr4 + 4];
#pragma unroll
            for (int nt2 = 0; nt2 < 2; nt2++) {
                int n = nt2 * 8 + grp;
                b0[nt2] = W2u[n * HS2 + kt * 8 + thr4];
                b1v[nt2] = W2u[n * HS2 + kt * 8 + thr4 + 4];
            }
#pragma unroll
            for (int nt2 = 0; nt2 < 2; nt2++) {
                uint32_t bb[2] = { b0[nt2], b1v[nt2] };
                mma_bf16(a2[nt2], a, bb);
            }
        }

#pragma unroll
        for (int nt2 = 0; nt2 < 2; nt2++) {
            int c = nt2 * 8 + thr4 * 2;
            int gr0 = row0 + rA;
            int gr1 = gr0 + 8;
            if (gr0 < NN)
                *(float2*)&g_hpart[blockIdx.x][gr0 * F_OUT + c] =
                    make_float2(a2[nt2][0], a2[nt2][1]);
            if (gr1 < NN)
                *(float2*)&g_hpart[blockIdx.x][gr1 * F_OUT + c] =
                    make_float2(a2[nt2][2], a2[nt2][3]);
        }
    }
}

// combine partials -> h; emit hy = dinv*h as fp16 (and y0 = hy, fp16)
__global__ void __launch_bounds__(256) k_hcombine(const float* __restrict__ b2) {
    int i = blockIdx.x * blockDim.x + threadIdx.x;   // over NN*4 quads
    if (i < NN * 4) {
        int node = i >> 2;
        const float4* p0 = (const float4*)g_hpart[0];
        const float4* p1 = (const float4*)g_hpart[1];
        const float4* b4 = (const float4*)b2;
        float4 a = p0[i], b = p1[i], c = __ldg(&b4[i & 3]);
        float di = g_dinv[node];
        float hx = (a.x + b.x + c.x) * di;
        float hyv = (a.y + b.y + c.y) * di;
        float hz = (a.z + b.z + c.z) * di;
        float hw = (a.w + b.w + c.w) * di;
        __half2 ha = __floats2half2_rn(hx, hyv);
        __half2 hb = __floats2half2_rn(hz, hw);
        uint2 w;
        w.x = *(uint32_t*)&ha;
        w.y = *(uint32_t*)&hb;
        g_hy16[i] = w;
        g_yA[i] = w;
    }
}

// ------------------------------------------------------------------
// Propagation in y-space (fp16 storage, fp32 accumulation)
// ------------------------------------------------------------------
__device__ __forceinline__ float4 y16_to_f4(uint2 r) {
    __half2 p0 = *(__half2*)&r.x;
    __half2 p1 = *(__half2*)&r.y;
    float2 f0 = __half22float2(p0);
    float2 f1 = __half22float2(p1);
    return make_float4(f0.x, f0.y, f1.x, f1.y);
}

__device__ __forceinline__ float4 prop_node_y(const uint2* __restrict__ yin,
                                              int node, int tc) {
    int s = g_ptr[node], e = g_ptr[node + 1];
    float4 acc = make_float4(0.f, 0.f, 0.f, 0.f);
    int j = s;
    for (; j + 1 < e; j += 2) {
        int s0 = __ldg(&g_esrc[j]);
        int s1 = __ldg(&g_esrc[j + 1]);
        float4 v0 = y16_to_f4(__ldg(&yin[s0 * 4 + tc]));
        float4 v1 = y16_to_f4(__ldg(&yin[s1 * 4 + tc]));
        acc.x += v0.x + v1.x;
        acc.y += v0.y + v1.y;
        acc.z += v0.z + v1.z;
        acc.w += v0.w + v1.w;
    }
    if (j < e) {
        int s0 = __ldg(&g_esrc[j]);
        float4 v0 = y16_to_f4(__ldg(&yin[s0 * 4 + tc]));
        acc.x += v0.x;
        acc.y += v0.y;
        acc.z += v0.z;
        acc.w += v0.w;
    }
    float4 vs = y16_to_f4(__ldg(&yin[node * 4 + tc]));
    float di = g_dinv[node];
    float c1 = (1.f - ALPHA) * di * di;
    float4 hy = y16_to_f4(__ldg(&g_hy16[node * 4 + tc]));
    float4 o;
    o.x = c1 * (acc.x + vs.x) + ALPHA * hy.x;
    o.y = c1 * (acc.y + vs.y) + ALPHA * hy.y;
    o.z = c1 * (acc.z + vs.z) + ALPHA * hy.z;
    o.w = c1 * (acc.w + vs.w) + ALPHA * hy.w;
    return o;
}

__global__ void __launch_bounds__(256) k_prop(int a_to_b) {
    const uint2* yin = a_to_b ? g_yA : g_yB;
    uint2* yout = a_to_b ? g_yB : g_yA;
    int node = blockIdx.x * 64 + (threadIdx.x >> 2);
    int tc = threadIdx.x & 3;
    if (node >= NN) return;
    float4 o = prop_node_y(yin, node, tc);
    __half2 ha = __floats2half2_rn(o.x, o.y);
    __half2 hb = __floats2half2_rn(o.z, o.w);
    uint2 w;
    w.x = *(uint32_t*)&ha;
    w.y = *(uint32_t*)&hb;
    yout[node * 4 + tc] = w;
}

// final step: y (fp32 regs) -> z = y/dinv -> log_softmax -> out. reads g_yB.
__global__ void __launch_bounds__(256) k_prop_lsm(float* __restrict__ out) {
    int node = blockIdx.x * 64 + (threadIdx.x >> 2);
    int tc = threadIdx.x & 3;
    if (node >= NN) return;
    float4 y = prop_node_y(g_yB, node, tc);
    float inv_di = 1.f / g_dinv[node];          // sqrt(deg)
    float4 v;
    v.x = y.x * inv_di; v.y = y.y * inv_di; v.z = y.z * inv_di; v.w = y.w * inv_di;
    float m = fmaxf(fmaxf(v.x, v.y), fmaxf(v.z, v.w));
    m = fmaxf(m, __shfl_xor_sync(0xffffffffu, m, 1, 4));
    m = fmaxf(m, __shfl_xor_sync(0xffffffffu, m, 2, 4));
    float s = expf(v.x - m) + expf(v.y - m) + expf(v.z - m) + expf(v.w - m);
    s += __shfl_xor_sync(0xffffffffu, s, 1, 4);
    s += __shfl_xor_sync(0xffffffffu, s, 2, 4);
    float ls = m + logf(s);
    float4 r;
    r.x = v.x - ls; r.y = v.y - ls; r.z = v.z - ls; r.w = v.w - ls;
    ((float4*)out)[node * 4 + tc] = r;
}

// ------------------------------------------------------------------
extern "C" void kernel_launch(void* const* d_in, const int* in_sizes, int n_in,
                              void* d_out, int out_size) {
    const float* x  = (const float*)d_in[0];
    const float* W1 = (const float*)d_in[1];
    const float* b1 = (const float*)d_in[2];
    const float* W2 = (const float*)d_in[3];
    const float* b2 = (const float*)d_in[4];
    const int* ei = (const int*)d_in[5];
    const int* src = ei;
    const int* dst = ei + NE;
    float* out = (float*)d_out;

    static cudaStream_t s_csr = nullptr;
    static cudaEvent_t ev_fork = nullptr, ev_dinv = nullptr, ev_join = nullptr;
    static bool init_done = false;
    if (!init_done) {
        cudaStreamCreateWithFlags(&s_csr, cudaStreamNonBlocking);
        cudaEventCreateWithFlags(&ev_fork, cudaEventDisableTiming);
        cudaEventCreateWithFlags(&ev_dinv, cudaEventDisableTiming);
        cudaEventCreateWithFlags(&ev_join, cudaEventDisableTiming);
        cudaFuncSetAttribute(k_mlp, cudaFuncAttributeMaxDynamicSharedMemorySize, SMEM_BYTES);
        init_done = true;
    }

    // fork
    cudaEventRecord(ev_fork, 0);
    cudaStreamWaitEvent(s_csr, ev_fork, 0);

    // --- CSR branch ---
    k_zero_counts<<<(NN + 255) / 256, 256, 0, s_csr>>>();
    k_count<<<(NE / 2 + 255) / 256, 256, 0, s_csr>>>((const int2*)dst);
    k_dinv<<<(NN + 255) / 256, 256, 0, s_csr>>>();
    cudaEventRecord(ev_dinv, s_csr);        // dinv ready early for hcombine
    k_scan1<<<NB_SCAN, 1024, 0, s_csr>>>();
    k_scan2<<<1, 128, 0, s_csr>>>();
    k_scan3<<<NB_SCAN, 1024, 0, s_csr>>>();
    k_fill<<<(NE + 255) / 256, 256, 0, s_csr>>>(src, dst);
    cudaEventRecord(ev_join, s_csr);

    // --- MLP branch (default stream) ---
    dim3 gm(2, MLP_GY);
    k_mlp<<<gm, 256, SMEM_BYTES>>>(x, W1, b1, W2);
    cudaStreamWaitEvent(0, ev_dinv, 0);     // hcombine needs dinv
    k_hcombine<<<(NN * 4 + 255) / 256, 256>>>(b2);

    // join (prop needs CSR)
    cudaStreamWaitEvent(0, ev_join, 0);

    // 9 intermediate y-steps (A->B->A...), step 8 ends in B; final fused step reads B
    for (int s = 0; s < KSTEPS - 1; s++)
        k_prop<<<(NN + 63) / 64, 256>>>((s & 1) ? 0 : 1);
    k_prop_lsm<<<(NN + 63) / 64, 256>>>(out);
}